// round 10
// baseline (speedup 1.0000x reference)
#include <cuda_runtime.h>

#define BB 8
#define HH 128
#define WWD 128
#define DD4 128          // D / 4 (float4 lanes)

// Scratch (allocation-free rule: __device__ globals)
// g_partial: [bh][half][slot][d4]; half0 slots {a0,a1,a2p,af}, half1 {a2p,a3,-,af}
__device__ float4 g_partial[BB * HH * 2 * 4 * DD4];
__device__ float4 g_sums[BB * 17 * DD4];   // [b][r][d4], r=0..15 regions, r=16 global

__device__ __forceinline__ float4 f4add(float4 a, float4 b) {
    return make_float4(a.x + b.x, a.y + b.y, a.z + b.z, a.w + b.w);
}
__device__ __forceinline__ float4 f4fma(float s, float4 a, float4 b) {
    return make_float4(fmaf(s, a.x, b.x), fmaf(s, a.y, b.y),
                       fmaf(s, a.z, b.z), fmaf(s, a.w, b.w));
}

// ---------------------------------------------------------------------------
// k1: half-row blocks for occupancy. grid = B*H*2 = 2048 blocks, 128 threads
// (~14 blocks/SM — doubles in-flight loads per SM vs 1024-block form).
// half 0: w in [0,64):  a0 (w<32), a1 (24<=w<56), a2p (48<=w), af
// half 1: w in [64,128): a2p (w<80), a3 (72<=w<104), af
// Slots as STORED: half0 {s0=a0, s1=a1, s2=a2p, slot3=af}
//                  half1 {s0=a2p, s1=a3, s2=0,  slot3=af}
// ---------------------------------------------------------------------------
__global__ __launch_bounds__(128) void k1_rowsums(const float4* __restrict__ feat) {
    const int bh   = blockIdx.x >> 1;
    const int half = blockIdx.x & 1;
    const int t    = threadIdx.x;
    const float4* row = feat + ((size_t)bh * WWD + half * 64) * DD4 + t;

    float4 s0 = make_float4(0.f, 0.f, 0.f, 0.f);
    float4 s1 = s0, s2 = s0, af = s0;

    if (half == 0) {
        #pragma unroll 4
        for (int w = 0; w < 64; ++w) {
            float4 v = __ldg(&row[(size_t)w * DD4]);
            af = f4add(af, v);
            if (w < 32)             s0 = f4add(s0, v);   // a0
            if (w >= 24 && w < 56)  s1 = f4add(s1, v);   // a1
            if (w >= 48)            s2 = f4add(s2, v);   // a2 part (48..63)
        }
    } else {
        #pragma unroll 4
        for (int w = 0; w < 64; ++w) {                   // global w = 64 + w
            float4 v = __ldg(&row[(size_t)w * DD4]);
            af = f4add(af, v);
            if (w < 16)             s0 = f4add(s0, v);   // a2 part (64..79)
            if (w >= 8 && w < 40)   s1 = f4add(s1, v);   // a3 (72..103)
        }
    }

    float4* p = g_partial + (size_t)blockIdx.x * 4 * DD4 + t;
    __stcs(&p[0 * DD4], s0);
    __stcs(&p[1 * DD4], s1);
    __stcs(&p[2 * DD4], s2);
    __stcs(&p[3 * DD4], af);
}

// ---------------------------------------------------------------------------
// k1b: reduce partials over h into 16 region sums + global sum.
// grid = B*17 blocks, 128 threads. L2-hot, ~3 us.
// Region (i,j): h in [24i, 24i+32).
//   j=0 -> half0 slot0;  j=1 -> half0 slot1
//   j=2 -> half0 slot2 + half1 slot0;  j=3 -> half1 slot1
// Global: half0 slot3 + half1 slot3 over all h.   (R9 bug: read slot2)
// ---------------------------------------------------------------------------
__global__ __launch_bounds__(128) void k1b_reduce() {
    const int b = blockIdx.x / 17;
    const int r = blockIdx.x % 17;
    const int t = threadIdx.x;

    float4 acc = make_float4(0.f, 0.f, 0.f, 0.f);
    if (r < 16) {
        const int i  = r >> 2;
        const int j  = r & 3;
        const int h0 = 24 * i;
        #pragma unroll 4
        for (int hh = 0; hh < 32; ++hh) {
            const size_t rowbase = (size_t)(b * HH + h0 + hh) * 2;   // block index of half0
            if (j == 0) {
                acc = f4add(acc, __ldcs(&g_partial[(rowbase * 4 + 0) * DD4 + t]));
            } else if (j == 1) {
                acc = f4add(acc, __ldcs(&g_partial[(rowbase * 4 + 1) * DD4 + t]));
            } else if (j == 2) {
                acc = f4add(acc, __ldcs(&g_partial[(rowbase * 4 + 2) * DD4 + t]));
                acc = f4add(acc, __ldcs(&g_partial[((rowbase + 1) * 4 + 0) * DD4 + t]));
            } else {
                acc = f4add(acc, __ldcs(&g_partial[((rowbase + 1) * 4 + 1) * DD4 + t]));
            }
        }
    } else {
        #pragma unroll 4
        for (int h = 0; h < HH; ++h) {
            const size_t rowbase = (size_t)(b * HH + h) * 2;
            acc = f4add(acc, __ldcs(&g_partial[(rowbase * 4 + 3) * DD4 + t]));
            acc = f4add(acc, __ldcs(&g_partial[((rowbase + 1) * 4 + 3) * DD4 + t]));
        }
    }
    g_sums[(size_t)(b * 17 + r) * DD4 + t] = acc;
}

// ---------------------------------------------------------------------------
// k2: elementwise pass, REVERSE w order (127 -> 0): consume the L2-resident
// w-tail left by k1's LRU before k2's own streaming evicts it.
// grid = B*H = 1024 blocks, 512 threads: threadIdx = wq*128 + t.
// Reads __ldcs, stores __stcs (measured best in R8).
// ---------------------------------------------------------------------------
__global__ __launch_bounds__(512) void k2_apply(const float4* __restrict__ feat,
                                                float4* __restrict__ out) {
    const int bh = blockIdx.x;
    const int b  = bh >> 7;
    const int h  = bh & 127;
    const int t  = threadIdx.x & 127;   // d4 lane
    const int wq = threadIdx.x >> 7;    // w quarter (reversed below)

    __shared__ float4 s_wc[WWD];        // {ww0..ww3} * coef, per w

    // per-h Gaussian weights (uniform across block)
    const float hc = h * (3.0f / 127.0f);
    float hwv[4];
    float HS = 0.f;
    #pragma unroll
    for (int i = 0; i < 4; ++i) {
        float d = hc - (float)i;
        hwv[i] = __expf(-0.125f * d * d);
        HS += hwv[i];
    }

    if (threadIdx.x < WWD) {
        const int w = threadIdx.x;
        const float wc = w * (3.0f / 127.0f);
        float e[4];
        float WS = 0.f;
        #pragma unroll
        for (int j = 0; j < 4; ++j) {
            float d = wc - (float)j;
            e[j] = __expf(-0.125f * d * d);
            WS += e[j];
        }
        const float c = 0.6f / (1024.0f * (HS * WS + 1e-8f));
        s_wc[w] = make_float4(e[0] * c, e[1] * c, e[2] * c, e[3] * c);
    }
    __syncthreads();

    // colagg[j] + global term for this d4 lane (g_sums tiny, L2-hot)
    const float4* srow = g_sums + (size_t)b * 17 * DD4 + t;
    float4 ca[4];
    #pragma unroll
    for (int j = 0; j < 4; ++j) ca[j] = make_float4(0.f, 0.f, 0.f, 0.f);
    #pragma unroll
    for (int i = 0; i < 4; ++i)
        #pragma unroll
        for (int j = 0; j < 4; ++j)
            ca[j] = f4fma(hwv[i], srow[(i * 4 + j) * DD4], ca[j]);

    float4 gs = srow[16 * DD4];
    const float gscale = 0.4f / 16384.0f;
    float4 base = make_float4(gs.x * gscale, gs.y * gscale, gs.z * gscale, gs.w * gscale);

    // Reverse quarter assignment: consume highest w first.
    const int rq = 3 - wq;
    const int w0 = rq * 32;
    const float4* frow = feat + ((size_t)bh * WWD + w0) * DD4 + t;
    float4*       orow = out  + ((size_t)bh * WWD + w0) * DD4 + t;

    #pragma unroll
    for (int g = 3; g >= 0; --g) {
        float4 v[8];
        #pragma unroll
        for (int k = 0; k < 8; ++k)
            v[k] = __ldcs(&frow[(size_t)(g * 8 + k) * DD4]);

        #pragma unroll
        for (int k = 0; k < 8; ++k) {
            const float4 wc = s_wc[w0 + g * 8 + k];
            float4 r;
            r.x = v[k].x + base.x + wc.x * ca[0].x + wc.y * ca[1].x + wc.z * ca[2].x + wc.w * ca[3].x;
            r.y = v[k].y + base.y + wc.x * ca[0].y + wc.y * ca[1].y + wc.z * ca[2].y + wc.w * ca[3].y;
            r.z = v[k].z + base.z + wc.x * ca[0].z + wc.y * ca[1].z + wc.z * ca[2].z + wc.w * ca[3].z;
            r.w = v[k].w + base.w + wc.x * ca[0].w + wc.y * ca[1].w + wc.z * ca[2].w + wc.w * ca[3].w;
            __stcs(&orow[(size_t)(g * 8 + k) * DD4], r);
        }
    }
}

// ---------------------------------------------------------------------------
extern "C" void kernel_launch(void* const* d_in, const int* in_sizes, int n_in,
                              void* d_out, int out_size) {
    const float4* feat = (const float4*)d_in[0];
    float4*       out  = (float4*)d_out;

    k1_rowsums<<<BB * HH * 2, 128>>>(feat);
    k1b_reduce<<<BB * 17, 128>>>();
    k2_apply<<<BB * HH, 512>>>(feat, out);
}

// round 12
// speedup vs baseline: 1.1015x; 1.1015x over previous
#include <cuda_runtime.h>

#define BB 8
#define HH 128
#define WWD 128
#define DD4 128          // D / 4 (float4 lanes)

// Scratch (allocation-free rule: __device__ globals)
__device__ float4 g_partial[BB * HH * 5 * DD4];  // [b][h][k][d4], k=0..3 w-region sums, k=4 full row
__device__ float4 g_sums[BB * 17 * DD4];         // [b][r][d4], r=0..15 region sums, r=16 global

__device__ __forceinline__ float4 f4add(float4 a, float4 b) {
    return make_float4(a.x + b.x, a.y + b.y, a.z + b.z, a.w + b.w);
}
__device__ __forceinline__ float4 f4fma(float s, float4 a, float4 b) {
    return make_float4(fmaf(s, a.x, b.x), fmaf(s, a.y, b.y),
                       fmaf(s, a.z, b.z), fmaf(s, a.w, b.w));
}

// ---------------------------------------------------------------------------
// k1: per (b,h) row — per-w-region partial sums + full row sum.
// grid = B*H = 1024 blocks, 128 threads (all co-resident, single wave).
// Cache policy (R7-verified): w<80 __ldcs (evict-first, don't pollute),
// w>=80 __ldg (allocate) — pins the w-tail (~96 MiB across rows) in L2.
// ---------------------------------------------------------------------------
__global__ __launch_bounds__(128) void k1_rowsums(const float4* __restrict__ feat) {
    const int bh = blockIdx.x;                 // b*128 + h
    const int t  = threadIdx.x;                // d4 lane
    const float4* row = feat + (size_t)bh * WWD * DD4 + t;

    float4 a0 = make_float4(0.f, 0.f, 0.f, 0.f);
    float4 a1 = a0, a2 = a0, a3 = a0, af = a0;

    // region j covers w in [24j, 24j+32)
    #pragma unroll 4
    for (int w = 0; w < 80; ++w) {
        float4 v = __ldcs(&row[(size_t)w * DD4]);   // evict-first
        af = f4add(af, v);
        if (w < 32)             a0 = f4add(a0, v);
        if (w >= 24 && w < 56)  a1 = f4add(a1, v);
        if (w >= 48 && w < 80)  a2 = f4add(a2, v);
        if (w >= 72)            a3 = f4add(a3, v);
    }
    #pragma unroll 4
    for (int w = 80; w < WWD; ++w) {
        float4 v = __ldg(&row[(size_t)w * DD4]);    // allocate (pin for k2)
        af = f4add(af, v);
        if (w < 104) a3 = f4add(a3, v);
    }

    float4* p = g_partial + (size_t)bh * 5 * DD4 + t;
    __stcs(&p[0 * DD4], a0);
    __stcs(&p[1 * DD4], a1);
    __stcs(&p[2 * DD4], a2);
    __stcs(&p[3 * DD4], a3);
    __stcs(&p[4 * DD4], af);
}

// ---------------------------------------------------------------------------
// k1b: reduce partials over h into 16 region sums + global sum.
// grid = B*17 blocks, 128 threads. __ldcs: g_partial dead after this and must
// not evict the pinned feature tail.
// ---------------------------------------------------------------------------
__global__ __launch_bounds__(128) void k1b_reduce() {
    const int b = blockIdx.x / 17;
    const int r = blockIdx.x % 17;
    const int t = threadIdx.x;

    float4 acc = make_float4(0.f, 0.f, 0.f, 0.f);
    if (r < 16) {
        const int i  = r >> 2;     // h-region index
        const int j  = r & 3;      // w-region index
        const int h0 = 24 * i;     // h-region covers [24i, 24i+32)
        #pragma unroll 8
        for (int hh = 0; hh < 32; ++hh) {
            float4 v = __ldcs(&g_partial[((size_t)(b * HH + h0 + hh) * 5 + j) * DD4 + t]);
            acc = f4add(acc, v);
        }
    } else {
        #pragma unroll 8
        for (int h = 0; h < HH; ++h) {
            float4 v = __ldcs(&g_partial[((size_t)(b * HH + h) * 5 + 4) * DD4 + t]);
            acc = f4add(acc, v);
        }
    }
    g_sums[(size_t)(b * 17 + r) * DD4 + t] = acc;
}

// ---------------------------------------------------------------------------
// k2: elementwise pass, REVERSE w order (127 -> 0): consume the PINNED
// w-tail [80,128) first, while it is still resident.
// grid = B*H = 1024 blocks, 512 threads: threadIdx = wq*128 + t.
// Reads __ldcs (hit still hits + demotes dead line; miss doesn't evict tail).
// Stores __stcs (never re-read; don't write-allocate over the tail).
// ---------------------------------------------------------------------------
__global__ __launch_bounds__(512) void k2_apply(const float4* __restrict__ feat,
                                                float4* __restrict__ out) {
    const int bh = blockIdx.x;
    const int b  = bh >> 7;
    const int h  = bh & 127;
    const int t  = threadIdx.x & 127;   // d4 lane
    const int wq = threadIdx.x >> 7;    // w quarter (reversed below)

    __shared__ float4 s_wc[WWD];        // {ww0..ww3} * coef, per w

    // per-h Gaussian weights (uniform across block)
    const float hc = h * (3.0f / 127.0f);
    float hwv[4];
    float HS = 0.f;
    #pragma unroll
    for (int i = 0; i < 4; ++i) {
        float d = hc - (float)i;
        hwv[i] = __expf(-0.125f * d * d);
        HS += hwv[i];
    }

    if (threadIdx.x < WWD) {
        const int w = threadIdx.x;
        const float wc = w * (3.0f / 127.0f);
        float e[4];
        float WS = 0.f;
        #pragma unroll
        for (int j = 0; j < 4; ++j) {
            float d = wc - (float)j;
            e[j] = __expf(-0.125f * d * d);
            WS += e[j];
        }
        const float c = 0.6f / (1024.0f * (HS * WS + 1e-8f));
        s_wc[w] = make_float4(e[0] * c, e[1] * c, e[2] * c, e[3] * c);
    }
    __syncthreads();

    // colagg[j] + global term for this d4 lane (g_sums tiny, L2-hot)
    const float4* srow = g_sums + (size_t)b * 17 * DD4 + t;
    float4 ca[4];
    #pragma unroll
    for (int j = 0; j < 4; ++j) ca[j] = make_float4(0.f, 0.f, 0.f, 0.f);
    #pragma unroll
    for (int i = 0; i < 4; ++i)
        #pragma unroll
        for (int j = 0; j < 4; ++j)
            ca[j] = f4fma(hwv[i], srow[(i * 4 + j) * DD4], ca[j]);

    float4 gs = srow[16 * DD4];
    const float gscale = 0.4f / 16384.0f;
    float4 base = make_float4(gs.x * gscale, gs.y * gscale, gs.z * gscale, gs.w * gscale);

    // Reverse quarter assignment: consume highest w (the pinned window) first.
    const int rq = 3 - wq;
    const int w0 = rq * 32;
    const float4* frow = feat + ((size_t)bh * WWD + w0) * DD4 + t;
    float4*       orow = out  + ((size_t)bh * WWD + w0) * DD4 + t;

    #pragma unroll
    for (int g = 3; g >= 0; --g) {
        float4 v[8];
        #pragma unroll
        for (int k = 0; k < 8; ++k)
            v[k] = __ldcs(&frow[(size_t)(g * 8 + k) * DD4]);

        #pragma unroll
        for (int k = 0; k < 8; ++k) {
            const float4 wc = s_wc[w0 + g * 8 + k];
            float4 r;
            r.x = v[k].x + base.x + wc.x * ca[0].x + wc.y * ca[1].x + wc.z * ca[2].x + wc.w * ca[3].x;
            r.y = v[k].y + base.y + wc.x * ca[0].y + wc.y * ca[1].y + wc.z * ca[2].y + wc.w * ca[3].y;
            r.z = v[k].z + base.z + wc.x * ca[0].z + wc.y * ca[1].z + wc.z * ca[2].z + wc.w * ca[3].z;
            r.w = v[k].w + base.w + wc.x * ca[0].w + wc.y * ca[1].w + wc.z * ca[2].w + wc.w * ca[3].w;
            __stcs(&orow[(size_t)(g * 8 + k) * DD4], r);
        }
    }
}

// ---------------------------------------------------------------------------
extern "C" void kernel_launch(void* const* d_in, const int* in_sizes, int n_in,
                              void* d_out, int out_size) {
    const float4* feat = (const float4*)d_in[0];
    float4*       out  = (float4*)d_out;

    k1_rowsums<<<BB * HH, 128>>>(feat);
    k1b_reduce<<<BB * 17, 128>>>();
    k2_apply<<<BB * HH, 512>>>(feat, out);
}

// round 13
// speedup vs baseline: 1.1813x; 1.0724x over previous
#include <cuda_runtime.h>

#define BB 8
#define HH 128
#define WWD 128
#define DD4 128          // D / 4 (float4 lanes)

// Scratch (allocation-free rule: __device__ globals)
__device__ float4 g_partial[BB * HH * 5 * DD4];  // [b][h][k][d4], k=0..3 w-region sums, k=4 full row
__device__ float4 g_sums[BB * 17 * DD4];         // [b][r][d4], r=0..15 region sums, r=16 global

__device__ __forceinline__ float4 f4add(float4 a, float4 b) {
    return make_float4(a.x + b.x, a.y + b.y, a.z + b.z, a.w + b.w);
}
__device__ __forceinline__ float4 f4fma(float s, float4 a, float4 b) {
    return make_float4(fmaf(s, a.x, b.x), fmaf(s, a.y, b.y),
                       fmaf(s, a.z, b.z), fmaf(s, a.w, b.w));
}

// ---------------------------------------------------------------------------
// k1: per (b,h) row — per-w-region partial sums + full row sum.
// grid = B*H = 1024 blocks, 128 threads. EXACT R2/R8 form (fastest: 44.7us).
// ---------------------------------------------------------------------------
__global__ __launch_bounds__(128) void k1_rowsums(const float4* __restrict__ feat) {
    const int bh = blockIdx.x;                 // b*128 + h
    const int t  = threadIdx.x;                // d4 lane
    const float4* row = feat + (size_t)bh * WWD * DD4 + t;

    float4 a0 = make_float4(0.f, 0.f, 0.f, 0.f);
    float4 a1 = a0, a2 = a0, a3 = a0, af = a0;

    #pragma unroll 4
    for (int w = 0; w < WWD; ++w) {
        float4 v = __ldg(&row[(size_t)w * DD4]);
        af = f4add(af, v);
        // region j covers w in [24j, 24j+32)
        if (w < 32)             a0 = f4add(a0, v);
        if (w >= 24 && w < 56)  a1 = f4add(a1, v);
        if (w >= 48 && w < 80)  a2 = f4add(a2, v);
        if (w >= 72 && w < 104) a3 = f4add(a3, v);
    }

    float4* p = g_partial + (size_t)bh * 5 * DD4 + t;
    p[0 * DD4] = a0;
    p[1 * DD4] = a1;
    p[2 * DD4] = a2;
    p[3 * DD4] = a3;
    p[4 * DD4] = af;
}

// ---------------------------------------------------------------------------
// k1b: reduce partials over h into 16 region sums + global sum.
// grid = B*17 blocks, 128 threads. __ldcs: g_partial dead after this and must
// not evict the LRU-resident feature tail.
// ---------------------------------------------------------------------------
__global__ __launch_bounds__(128) void k1b_reduce() {
    const int b = blockIdx.x / 17;
    const int r = blockIdx.x % 17;
    const int t = threadIdx.x;

    float4 acc = make_float4(0.f, 0.f, 0.f, 0.f);
    if (r < 16) {
        const int i  = r >> 2;     // h-region index
        const int j  = r & 3;      // w-region index
        const int h0 = 24 * i;     // h-region covers [24i, 24i+32)
        #pragma unroll 8
        for (int hh = 0; hh < 32; ++hh) {
            float4 v = __ldcs(&g_partial[((size_t)(b * HH + h0 + hh) * 5 + j) * DD4 + t]);
            acc = f4add(acc, v);
        }
    } else {
        #pragma unroll 8
        for (int h = 0; h < HH; ++h) {
            float4 v = __ldcs(&g_partial[((size_t)(b * HH + h) * 5 + 4) * DD4 + t]);
            acc = f4add(acc, v);
        }
    }
    g_sums[(size_t)(b * 17 + r) * DD4 + t] = acc;
}

// ---------------------------------------------------------------------------
// k2: elementwise pass with LONG burst groups: 16 loads then 16 stores per
// group (half the read<->write direction switches vs 8-deep).
// grid = B*H = 1024 blocks, 256 threads: threadIdx = s*128 + t
//   t = d4 lane, s = w-half (s=0 -> high half [64,128), s=1 -> low [0,64)).
// Each thread: 64 w as 4 groups of 16, groups high-w first (tail harvest).
// Reads __ldcs, stores __stcs (R8-measured best policies).
// ---------------------------------------------------------------------------
__global__ __launch_bounds__(256) void k2_apply(const float4* __restrict__ feat,
                                                float4* __restrict__ out) {
    const int bh = blockIdx.x;
    const int b  = bh >> 7;
    const int h  = bh & 127;
    const int t  = threadIdx.x & 127;   // d4 lane
    const int s  = threadIdx.x >> 7;    // w-half selector

    __shared__ float4 s_wc[WWD];        // {ww0..ww3} * coef, per w

    // per-h Gaussian weights (uniform across block)
    const float hc = h * (3.0f / 127.0f);
    float hwv[4];
    float HS = 0.f;
    #pragma unroll
    for (int i = 0; i < 4; ++i) {
        float d = hc - (float)i;
        hwv[i] = __expf(-0.125f * d * d);
        HS += hwv[i];
    }

    if (threadIdx.x < WWD) {
        const int w = threadIdx.x;
        const float wc = w * (3.0f / 127.0f);
        float e[4];
        float WS = 0.f;
        #pragma unroll
        for (int j = 0; j < 4; ++j) {
            float d = wc - (float)j;
            e[j] = __expf(-0.125f * d * d);
            WS += e[j];
        }
        const float c = 0.6f / (1024.0f * (HS * WS + 1e-8f));
        s_wc[w] = make_float4(e[0] * c, e[1] * c, e[2] * c, e[3] * c);
    }
    __syncthreads();

    // colagg[j] + global term for this d4 lane (g_sums tiny, L2-hot)
    const float4* srow = g_sums + (size_t)b * 17 * DD4 + t;
    float4 ca[4];
    #pragma unroll
    for (int j = 0; j < 4; ++j) ca[j] = make_float4(0.f, 0.f, 0.f, 0.f);
    #pragma unroll
    for (int i = 0; i < 4; ++i)
        #pragma unroll
        for (int j = 0; j < 4; ++j)
            ca[j] = f4fma(hwv[i], srow[(i * 4 + j) * DD4], ca[j]);

    float4 gs = srow[16 * DD4];
    const float gscale = 0.4f / 16384.0f;
    float4 base = make_float4(gs.x * gscale, gs.y * gscale, gs.z * gscale, gs.w * gscale);

    // Half assignment: s=0 takes high w-half first (L2 tail), s=1 low half.
    const int w0 = (1 - s) * 64;        // start of this thread's 64-w range
    const float4* frow = feat + (size_t)bh * WWD * DD4 + t;
    float4*       orow = out  + (size_t)bh * WWD * DD4 + t;

    // 4 groups of 16, processed high-w first within the half.
    #pragma unroll
    for (int g = 3; g >= 0; --g) {
        const int wb = w0 + g * 16;
        float4 v[16];
        #pragma unroll
        for (int k = 0; k < 16; ++k)
            v[k] = __ldcs(&frow[(size_t)(wb + k) * DD4]);

        #pragma unroll
        for (int k = 0; k < 16; ++k) {
            const float4 wc = s_wc[wb + k];
            float4 r;
            r.x = v[k].x + base.x + wc.x * ca[0].x + wc.y * ca[1].x + wc.z * ca[2].x + wc.w * ca[3].x;
            r.y = v[k].y + base.y + wc.x * ca[0].y + wc.y * ca[1].y + wc.z * ca[2].y + wc.w * ca[3].y;
            r.z = v[k].z + base.z + wc.x * ca[0].z + wc.y * ca[1].z + wc.z * ca[2].z + wc.w * ca[3].z;
            r.w = v[k].w + base.w + wc.x * ca[0].w + wc.y * ca[1].w + wc.z * ca[2].w + wc.w * ca[3].w;
            __stcs(&orow[(size_t)(wb + k) * DD4], r);
        }
    }
}

// ---------------------------------------------------------------------------
extern "C" void kernel_launch(void* const* d_in, const int* in_sizes, int n_in,
                              void* d_out, int out_size) {
    const float4* feat = (const float4*)d_in[0];
    float4*       out  = (float4*)d_out;

    k1_rowsums<<<BB * HH, 128>>>(feat);
    k1b_reduce<<<BB * 17, 128>>>();
    k2_apply<<<BB * HH, 256>>>(feat, out);
}